// round 7
// baseline (speedup 1.0000x reference)
#include <cuda_runtime.h>
#include <cuda_bf16.h>

#define B_DIM 64
#define T_DIM 512
#define M_DIM 512
#define PAD_INDEX 1
#define LAMBDA1 0.02f
#define LAMBDA2 0.1f

__global__ void zero_out_kernel(float* out) { out[0] = 0.0f; }

// One CTA per t. 256 threads = 8 warps; warp w handles b = w + 8k, k=0..7.
// Each lane holds 16 floats of the 512-wide row: float4 chunks at
// float4-index (lane + 32c), c=0..3  => m = 4*(lane+32c) .. +3.
//
// Two phases (outputs stream, then embedding gathers), each a depth-3
// software pipeline, sharing one 16-reg accumulator array. 85-reg budget
// -> 3 CTAs/SM (24 warps) vs 2 before.
__global__ __launch_bounds__(256, 3) void vmf_loss_kernel(
    const float* __restrict__ outputs,    // [B,T,M]  read-once
    const int*   __restrict__ targets,    // [B,T]
    const float* __restrict__ embedding,  // [V,M]
    float* __restrict__ out)
{
    const int t    = blockIdx.x;
    const int tid  = threadIdx.x;
    const int w    = tid >> 5;
    const int lane = tid & 31;

    __shared__ float shf[8 * 512];        // 16 KB combine buffer
    __shared__ float sh_dot[8], sh_a[8], sh_nv[8];
    float4* shv4 = (float4*)shf;          // [warp][128] float4

    float acc[16];
#pragma unroll
    for (int i = 0; i < 16; i++) acc[i] = 0.0f;

    float4 buf[3][4];

    // ================= PHASE 1: outputs =================
    float sum_a = 0.0f;   // lane-uniform
#pragma unroll
    for (int s = 0; s < 2; s++) {
        const float4* orow =
            (const float4*)(outputs + ((size_t)(w + 8 * s) * T_DIM + t) * M_DIM);
#pragma unroll
        for (int c = 0; c < 4; c++) buf[s][c] = __ldlu(&orow[lane + 32 * c]);
    }

#pragma unroll
    for (int k = 0; k < 8; k++) {
        if (k + 2 < 8) {
            const float4* orow =
                (const float4*)(outputs +
                                ((size_t)(w + 8 * (k + 2)) * T_DIM + t) * M_DIM);
#pragma unroll
            for (int c = 0; c < 4; c++)
                buf[(k + 2) % 3][c] = __ldlu(&orow[lane + 32 * c]);
        }
        const float4* o = buf[k % 3];

        float ss = 0.0f;
#pragma unroll
        for (int c = 0; c < 4; c++)
            ss += o[c].x * o[c].x + o[c].y * o[c].y +
                  o[c].z * o[c].z + o[c].w * o[c].w;
#pragma unroll
        for (int off = 16; off > 0; off >>= 1)
            ss += __shfl_xor_sync(0xffffffffu, ss, off);

        const float inv_o = rsqrtf(fmaxf(ss, 1e-24f));
#pragma unroll
        for (int c = 0; c < 4; c++) {
            acc[c * 4 + 0] += o[c].x * inv_o;
            acc[c * 4 + 1] += o[c].y * inv_o;
            acc[c * 4 + 2] += o[c].z * inv_o;
            acc[c * 4 + 3] += o[c].w * inv_o;
        }

        // logC_m(kappa), v = M/2-1 = 255:
        //   sqrt(256^2 + z^2) - 254*log(254 + sqrt(254^2 + z^2))
        const float kappa = sqrtf(ss);
        const float logc  = sqrtf(65536.0f + ss)
                          - 254.0f * logf(254.0f + sqrtf(64516.0f + ss));
        sum_a += (-logc + LAMBDA1 * kappa);
    }

    // combine pass A: s_out partials (thread owns m = tid and tid+256)
#pragma unroll
    for (int c = 0; c < 4; c++)
        shv4[w * 128 + lane + 32 * c] =
            make_float4(acc[c * 4 + 0], acc[c * 4 + 1],
                        acc[c * 4 + 2], acc[c * 4 + 3]);
    __syncthreads();

    float so0 = 0.0f, so1 = 0.0f;
#pragma unroll
    for (int ww = 0; ww < 8; ww++) {
        so0 += shf[ww * 512 + tid];
        so1 += shf[ww * 512 + tid + 256];
    }
    __syncthreads();   // protect shf before pass B overwrites

    // ================= PHASE 2: embedding gathers =================
#pragma unroll
    for (int i = 0; i < 16; i++) acc[i] = 0.0f;
    float n_valid = 0.0f;   // lane-uniform

    int tg[8];
#pragma unroll
    for (int k = 0; k < 8; k++)
        tg[k] = __ldg(&targets[(w + 8 * k) * T_DIM + t]);

#pragma unroll
    for (int s = 0; s < 2; s++) {
        const float4* erow = (const float4*)(embedding + (size_t)tg[s] * M_DIM);
#pragma unroll
        for (int c = 0; c < 4; c++) buf[s][c] = __ldg(&erow[lane + 32 * c]);
    }

#pragma unroll
    for (int k = 0; k < 8; k++) {
        if (k + 2 < 8) {
            const float4* erow =
                (const float4*)(embedding + (size_t)tg[k + 2] * M_DIM);
#pragma unroll
            for (int c = 0; c < 4; c++)
                buf[(k + 2) % 3][c] = __ldg(&erow[lane + 32 * c]);
        }
        const float4* e = buf[k % 3];

        float es = 0.0f;
#pragma unroll
        for (int c = 0; c < 4; c++)
            es += e[c].x * e[c].x + e[c].y * e[c].y +
                  e[c].z * e[c].z + e[c].w * e[c].w;
#pragma unroll
        for (int off = 16; off > 0; off >>= 1)
            es += __shfl_xor_sync(0xffffffffu, es, off);

        const float mask  = (tg[k] != PAD_INDEX) ? 1.0f : 0.0f;
        const float inv_e = mask * rsqrtf(fmaxf(es, 1e-24f));
        n_valid += mask;
#pragma unroll
        for (int c = 0; c < 4; c++) {
            acc[c * 4 + 0] += e[c].x * inv_e;
            acc[c * 4 + 1] += e[c].y * inv_e;
            acc[c * 4 + 2] += e[c].z * inv_e;
            acc[c * 4 + 3] += e[c].w * inv_e;
        }
    }

    // combine pass B: s_trg partials, then dot with cached s_out partials
#pragma unroll
    for (int c = 0; c < 4; c++)
        shv4[w * 128 + lane + 32 * c] =
            make_float4(acc[c * 4 + 0], acc[c * 4 + 1],
                        acc[c * 4 + 2], acc[c * 4 + 3]);
    __syncthreads();

    float st0 = 0.0f, st1 = 0.0f;
#pragma unroll
    for (int ww = 0; ww < 8; ww++) {
        st0 += shf[ww * 512 + tid];
        st1 += shf[ww * 512 + tid + 256];
    }

    float dp = so0 * st0 + so1 * st1;
#pragma unroll
    for (int off = 16; off > 0; off >>= 1)
        dp += __shfl_xor_sync(0xffffffffu, dp, off);

    if (lane == 0) {
        sh_dot[w] = dp;
        sh_a[w]   = sum_a;
        sh_nv[w]  = n_valid;
    }
    __syncthreads();

    if (tid == 0) {
        float dot = 0.0f, sa = 0.0f, nv = 0.0f;
#pragma unroll
        for (int i = 0; i < 8; i++) {
            dot += sh_dot[i];
            sa  += sh_a[i];
            nv  += sh_nv[i];
        }
        const float val = nv * sa - LAMBDA2 * dot;
        atomicAdd(out, val);
    }
}

extern "C" void kernel_launch(void* const* d_in, const int* in_sizes, int n_in,
                              void* d_out, int out_size) {
    const float* outputs   = (const float*)d_in[0];
    const int*   targets   = (const int*)d_in[1];
    const float* embedding = (const float*)d_in[2];
    float* out = (float*)d_out;

    zero_out_kernel<<<1, 1>>>(out);
    vmf_loss_kernel<<<T_DIM, 256>>>(outputs, targets, embedding, out);
}